// round 10
// baseline (speedup 1.0000x reference)
#include <cuda_runtime.h>
#include <cuda_fp16.h>
#include <math.h>

#define BB      2
#define SEQ     2048
#define DMODEL  1024
#define NHEAD   16
#define DHEAD   64
#define NTOK    (BB * SEQ)        // 4096
#define NBH     (BB * NHEAD)      // 32
#define NITILE  (SEQ / 128)       // 16
#define ATTN_SCALE 0.125f         // 1/sqrt(64)

// ---------------------------------------------------------------------------
// Scratch
// ---------------------------------------------------------------------------
__device__ float  g_Q [(size_t)NTOK * DMODEL];
__device__ float  g_K [(size_t)NTOK * DMODEL];
__device__ float  g_V [(size_t)NTOK * DMODEL];
__device__ float  g_X [(size_t)NTOK * DMODEL];
__device__ __half g_SC[(size_t)NBH * SEQ * SEQ];    // scaled scores, fp16 (268MB)
__device__ float  g_PM[(size_t)NBH * NITILE * SEQ]; // per-itile col max
__device__ float  g_PS[(size_t)NBH * NITILE * SEQ]; // per-itile col sumexp
__device__ float  g_CM[NBH * SEQ];                  // global col max
__device__ float  g_CR[NBH * SEQ];                  // global 1/sum

// ---------------------------------------------------------------------------
// Helpers
// ---------------------------------------------------------------------------
__device__ __forceinline__ float tfbits(float x) {
    unsigned r;
    asm("cvt.rna.tf32.f32 %0, %1;" : "=r"(r) : "f"(x));
    return __uint_as_float(r);
}
__device__ __forceinline__ float4 tf4(float4 v) {
    return make_float4(tfbits(v.x), tfbits(v.y), tfbits(v.z), tfbits(v.w));
}
__device__ __forceinline__ unsigned ub(float x) { return __float_as_uint(x); }

__device__ __forceinline__ void mma_tf32(float* c, const unsigned* a, const unsigned* b) {
    asm volatile(
        "mma.sync.aligned.m16n8k8.row.col.f32.tf32.tf32.f32 "
        "{%0,%1,%2,%3}, {%4,%5,%6,%7}, {%8,%9}, {%0,%1,%2,%3};"
        : "+f"(c[0]), "+f"(c[1]), "+f"(c[2]), "+f"(c[3])
        : "r"(a[0]), "r"(a[1]), "r"(a[2]), "r"(a[3]), "r"(b[0]), "r"(b[1]));
}

// ---------------------------------------------------------------------------
// Projection GEMM (tf32, pre-converted smem): C[M,1024] = A[M,1024] @ W + bias
// 128x128 block, BK=32, register-staged LDG->cvt->STS (R7-verified structure).
// gridDim.z selects the (A,W,bias,C) set.
// ---------------------------------------------------------------------------
__global__ __launch_bounds__(256, 2) void proj_tf32(
    const float* __restrict__ A0, const float* __restrict__ A1, const float* __restrict__ A2,
    const float* __restrict__ W0, const float* __restrict__ W1, const float* __restrict__ W2,
    const float* __restrict__ b0_, const float* __restrict__ b1_, const float* __restrict__ b2_,
    float* __restrict__ C0, float* __restrict__ C1, float* __restrict__ C2)
{
    constexpr int N = DMODEL, K = DMODEL;
    __shared__ float As[128][36];    // [m][k]; frag banks 4g+t distinct
    __shared__ float Bs[32][136];    // [k][n]; frag banks 8t+g distinct

    const int z = blockIdx.z;
    const float* A    = z == 0 ? A0  : (z == 1 ? A1  : A2);
    const float* W    = z == 0 ? W0  : (z == 1 ? W1  : W2);
    const float* bias = z == 0 ? b0_ : (z == 1 ? b1_ : b2_);
    float*       C    = z == 0 ? C0  : (z == 1 ? C1  : C2);

    const int tid  = threadIdx.x;
    const int brow = blockIdx.y * 128;
    const int bcol = blockIdx.x * 128;
    const int w = tid >> 5, lane = tid & 31;
    const int g = lane >> 2, t = lane & 3;
    const int warpM = (w >> 2) * 64, warpN = (w & 3) * 32;

    const int ar = tid >> 3, ac4 = (tid & 7) * 4;    // A: rows ar+i*32, k-cols ac4
    const int br = tid >> 5, bc4 = (tid & 31) * 4;   // B: rows br+i*8,  n-cols bc4

    const float* Ap = A + (size_t)(brow + ar) * K + ac4;
    const float* Wp = W + (size_t)br * N + bcol + bc4;

    float4 ra[4], rb[4];
#pragma unroll
    for (int i = 0; i < 4; i++) ra[i] = *(const float4*)(Ap + (size_t)i * 32 * K);
#pragma unroll
    for (int i = 0; i < 4; i++) rb[i] = *(const float4*)(Wp + (size_t)i * 8 * N);

    float acc[4][4][4];
#pragma unroll
    for (int mt = 0; mt < 4; mt++)
#pragma unroll
        for (int nt = 0; nt < 4; nt++)
#pragma unroll
            for (int i = 0; i < 4; i++) acc[mt][nt][i] = 0.f;

    for (int k0 = 0; k0 < K; k0 += 32) {
#pragma unroll
        for (int i = 0; i < 4; i++) *(float4*)&As[ar + i * 32][ac4] = tf4(ra[i]);
#pragma unroll
        for (int i = 0; i < 4; i++) *(float4*)&Bs[br + i * 8][bc4]  = tf4(rb[i]);
        __syncthreads();

        if (k0 + 32 < K) {
#pragma unroll
            for (int i = 0; i < 4; i++)
                ra[i] = *(const float4*)(Ap + k0 + 32 + (size_t)i * 32 * K);
#pragma unroll
            for (int i = 0; i < 4; i++)
                rb[i] = *(const float4*)(Wp + (size_t)(k0 + 32 + i * 8) * N);
        }

#pragma unroll
        for (int ks = 0; ks < 4; ks++) {
            const int k = ks * 8;
            unsigned bfr[4][2];
#pragma unroll
            for (int nt = 0; nt < 4; nt++) {
                int c = warpN + nt * 8 + g;
                bfr[nt][0] = ub(Bs[k + t][c]);
                bfr[nt][1] = ub(Bs[k + t + 4][c]);
            }
#pragma unroll
            for (int mt = 0; mt < 4; mt++) {
                int r = warpM + mt * 16 + g;
                unsigned af[4] = { ub(As[r][k + t]),     ub(As[r + 8][k + t]),
                                   ub(As[r][k + t + 4]), ub(As[r + 8][k + t + 4]) };
#pragma unroll
                for (int nt = 0; nt < 4; nt++) mma_tf32(acc[mt][nt], af, bfr[nt]);
            }
        }
        __syncthreads();
    }

#pragma unroll
    for (int mt = 0; mt < 4; mt++) {
        int r0 = brow + warpM + mt * 16 + g;
#pragma unroll
        for (int nt = 0; nt < 4; nt++) {
            int c = bcol + warpN + nt * 8 + 2 * t;
            float bb0 = bias[c], bb1 = bias[c + 1];
            *(float2*)&C[(size_t)r0 * N + c]       = make_float2(acc[mt][nt][0] + bb0, acc[mt][nt][1] + bb1);
            *(float2*)&C[(size_t)(r0 + 8) * N + c] = make_float2(acc[mt][nt][2] + bb0, acc[mt][nt][3] + bb1);
        }
    }
}

// ---------------------------------------------------------------------------
// QK^T scores (tf32 NT) + fused per-tile column stats.
// Stores fp16 scaled scores; fp32 (max, sumexp) partials per 128-row i-tile.
// ---------------------------------------------------------------------------
__global__ __launch_bounds__(256, 2) void qk_tf32()
{
    __shared__ float Qs[128][36];
    __shared__ float Ks[128][36];
    __shared__ float Sm2[2][128];
    __shared__ float Ss2[2][128];

    const int tid = threadIdx.x;
    const int bh  = blockIdx.z, b = bh >> 4, h = bh & 15;
    const int browi = blockIdx.y * 128;
    const int bcolj = blockIdx.x * 128;

    const float* Qb = g_Q + (size_t)b * SEQ * DMODEL + (size_t)h * DHEAD;
    const float* Kb = g_K + (size_t)b * SEQ * DMODEL + (size_t)h * DHEAD;
    __half*      Cb = g_SC + (size_t)bh * SEQ * SEQ;

    const int w = tid >> 5, lane = tid & 31;
    const int g = lane >> 2, t = lane & 3;
    const int warpM = (w >> 2) * 64, warpN = (w & 3) * 32;

    const int lr = tid >> 3, lc4 = (tid & 7) * 4;
    const float* Qp = Qb + (size_t)(browi + lr) * DMODEL + lc4;
    const float* Kp = Kb + (size_t)(bcolj + lr) * DMODEL + lc4;

    float4 rq[4], rk[4];
#pragma unroll
    for (int i = 0; i < 4; i++) {
        rq[i] = *(const float4*)(Qp + (size_t)i * 32 * DMODEL);
        rk[i] = *(const float4*)(Kp + (size_t)i * 32 * DMODEL);
    }

    float acc[4][4][4];
#pragma unroll
    for (int mt = 0; mt < 4; mt++)
#pragma unroll
        for (int nt = 0; nt < 4; nt++)
#pragma unroll
            for (int i = 0; i < 4; i++) acc[mt][nt][i] = 0.f;

    for (int k0 = 0; k0 < DHEAD; k0 += 32) {
#pragma unroll
        for (int i = 0; i < 4; i++) {
            *(float4*)&Qs[lr + i * 32][lc4] = tf4(rq[i]);
            *(float4*)&Ks[lr + i * 32][lc4] = tf4(rk[i]);
        }
        __syncthreads();

        if (k0 == 0) {
#pragma unroll
            for (int i = 0; i < 4; i++) {
                rq[i] = *(const float4*)(Qp + 32 + (size_t)i * 32 * DMODEL);
                rk[i] = *(const float4*)(Kp + 32 + (size_t)i * 32 * DMODEL);
            }
        }

#pragma unroll
        for (int ks = 0; ks < 4; ks++) {
            const int k = ks * 8;
            unsigned bfr[4][2];
#pragma unroll
            for (int nt = 0; nt < 4; nt++) {
                int c = warpN + nt * 8 + g;
                bfr[nt][0] = ub(Ks[c][k + t]);
                bfr[nt][1] = ub(Ks[c][k + t + 4]);
            }
#pragma unroll
            for (int mt = 0; mt < 4; mt++) {
                int r = warpM + mt * 16 + g;
                unsigned af[4] = { ub(Qs[r][k + t]),     ub(Qs[r + 8][k + t]),
                                   ub(Qs[r][k + t + 4]), ub(Qs[r + 8][k + t + 4]) };
#pragma unroll
                for (int nt = 0; nt < 4; nt++) mma_tf32(acc[mt][nt], af, bfr[nt]);
            }
        }
        __syncthreads();
    }

    // scale, store fp16 scores
#pragma unroll
    for (int mt = 0; mt < 4; mt++)
#pragma unroll
        for (int nt = 0; nt < 4; nt++)
#pragma unroll
            for (int i = 0; i < 4; i++) acc[mt][nt][i] *= ATTN_SCALE;

#pragma unroll
    for (int mt = 0; mt < 4; mt++) {
        int r0 = browi + warpM + mt * 16 + g;
#pragma unroll
        for (int nt = 0; nt < 4; nt++) {
            int c = bcolj + warpN + nt * 8 + 2 * t;
            *(__half2*)&Cb[(size_t)r0 * SEQ + c] =
                __floats2half2_rn(acc[mt][nt][0], acc[mt][nt][1]);
            *(__half2*)&Cb[(size_t)(r0 + 8) * SEQ + c] =
                __floats2half2_rn(acc[mt][nt][2], acc[mt][nt][3]);
        }
    }

    // fused column stats over this tile's 128 rows (fp32)
#pragma unroll
    for (int nt = 0; nt < 4; nt++) {
        float m0 = -1e30f, m1 = -1e30f;
#pragma unroll
        for (int mt = 0; mt < 4; mt++) {
            m0 = fmaxf(m0, fmaxf(acc[mt][nt][0], acc[mt][nt][2]));
            m1 = fmaxf(m1, fmaxf(acc[mt][nt][1], acc[mt][nt][3]));
        }
#pragma unroll
        for (int off = 4; off < 32; off <<= 1) {
            m0 = fmaxf(m0, __shfl_xor_sync(0xffffffffu, m0, off));
            m1 = fmaxf(m1, __shfl_xor_sync(0xffffffffu, m1, off));
        }
        float s0 = 0.f, s1 = 0.f;
#pragma unroll
        for (int mt = 0; mt < 4; mt++) {
            s0 += __expf(acc[mt][nt][0] - m0) + __expf(acc[mt][nt][2] - m0);
            s1 += __expf(acc[mt][nt][1] - m1) + __expf(acc[mt][nt][3] - m1);
        }
#pragma unroll
        for (int off = 4; off < 32; off <<= 1) {
            s0 += __shfl_xor_sync(0xffffffffu, s0, off);
            s1 += __shfl_xor_sync(0xffffffffu, s1, off);
        }
        if (g == 0) {
            int c = warpN + nt * 8 + 2 * t;
            int half_ = w >> 2;
            Sm2[half_][c]     = m0;  Ss2[half_][c]     = s0;
            Sm2[half_][c + 1] = m1;  Ss2[half_][c + 1] = s1;
        }
    }
    __syncthreads();
    if (tid < 128) {
        float ma = Sm2[0][tid], mb = Sm2[1][tid];
        float m  = fmaxf(ma, mb);
        float s  = Ss2[0][tid] * __expf(ma - m) + Ss2[1][tid] * __expf(mb - m);
        size_t off = ((size_t)bh * NITILE + blockIdx.y) * SEQ + bcolj + tid;
        g_PM[off] = m;
        g_PS[off] = s;
    }
}

// ---------------------------------------------------------------------------
// Merge per-itile partials -> global column (max, 1/sum).
// ---------------------------------------------------------------------------
__global__ __launch_bounds__(256) void stats_reduce()
{
    const int bh = blockIdx.y;
    const int j  = blockIdx.x * 256 + threadIdx.x;

    float m = -1e30f, s = 0.f;
#pragma unroll
    for (int it = 0; it < NITILE; it++) {
        size_t off = ((size_t)bh * NITILE + it) * SEQ + j;
        float mp = g_PM[off], sp = g_PS[off];
        float mn = fmaxf(m, mp);
        s = s * __expf(m - mn) + sp * __expf(mp - mn);
        m = mn;
    }
    g_CM[bh * SEQ + j] = m;
    g_CR[bh * SEQ + j] = 1.0f / s;
}

// ---------------------------------------------------------------------------
// AV GEMM (tf32) with fused softmax on P fill, fp16 score loads.
// 128(i) x 64(d) block, BK=32 over j (R7-verified structure).
// ---------------------------------------------------------------------------
__global__ __launch_bounds__(256, 2) void av_tf32()
{
    __shared__ float Ps[128][36];   // [i][j-local]
    __shared__ float Vs[32][72];    // [j-local][d]

    const int tid = threadIdx.x;
    const int bh  = blockIdx.y, b = bh >> 4, h = bh & 15;
    const int browi = blockIdx.x * 128;

    const __half* Sb = g_SC + (size_t)bh * SEQ * SEQ;
    const float*  cm = g_CM + bh * SEQ;
    const float*  cr = g_CR + bh * SEQ;
    const float*  Vb = g_V + (size_t)b * SEQ * DMODEL + (size_t)h * DHEAD;

    const int w = tid >> 5, lane = tid & 31;
    const int g = lane >> 2, t = lane & 3;
    const int warpM = (w >> 1) * 32, warpN = (w & 1) * 32;

    const int pr = tid >> 3, pc4 = (tid & 7) * 4;    // P: rows pr+i*32, cols pc4..+3
    const int vr = tid >> 4, vc4 = (tid & 15) * 4;   // V: rows vr+i*16

    uint2  rs[4];                 // 4 half scores per row, 4 rows
    float4 rv[2], rm, rr;
#pragma unroll
    for (int i = 0; i < 4; i++)
        rs[i] = *(const uint2*)(Sb + (size_t)(browi + pr + i * 32) * SEQ + pc4);
#pragma unroll
    for (int i = 0; i < 2; i++)
        rv[i] = *(const float4*)(Vb + (size_t)(vr + i * 16) * DMODEL + vc4);
    rm = *(const float4*)&cm[pc4];
    rr = *(const float4*)&cr[pc4];

    float acc[2][4][4];
#pragma unroll
    for (int mt = 0; mt < 2; mt++)
#pragma unroll
        for (int nt = 0; nt < 4; nt++)
#pragma unroll
            for (int i = 0; i < 4; i++) acc[mt][nt][i] = 0.f;

    for (int k0 = 0; k0 < SEQ; k0 += 32) {
        // P fill: half->float, exp-normalize, tf32 cvt
#pragma unroll
        for (int i = 0; i < 4; i++) {
            float2 f01 = __half22float2(*(__half2*)&rs[i].x);
            float2 f23 = __half22float2(*(__half2*)&rs[i].y);
            *(float4*)&Ps[pr + i * 32][pc4] = make_float4(
                tfbits(__expf(f01.x - rm.x) * rr.x),
                tfbits(__expf(f01.y - rm.y) * rr.y),
                tfbits(__expf(f23.x - rm.z) * rr.z),
                tfbits(__expf(f23.y - rm.w) * rr.w));
        }
#pragma unroll
        for (int i = 0; i < 2; i++) *(float4*)&Vs[vr + i * 16][vc4] = tf4(rv[i]);
        __syncthreads();

        if (k0 + 32 < SEQ) {
            const int kn = k0 + 32;
#pragma unroll
            for (int i = 0; i < 4; i++)
                rs[i] = *(const uint2*)(Sb + (size_t)(browi + pr + i * 32) * SEQ + kn + pc4);
#pragma unroll
            for (int i = 0; i < 2; i++)
                rv[i] = *(const float4*)(Vb + (size_t)(kn + vr + i * 16) * DMODEL + vc4);
            rm = *(const float4*)&cm[kn + pc4];
            rr = *(const float4*)&cr[kn + pc4];
        }

#pragma unroll
        for (int ks = 0; ks < 4; ks++) {
            const int k = ks * 8;
            unsigned bfr[4][2];
#pragma unroll
            for (int nt = 0; nt < 4; nt++) {
                int c = warpN + nt * 8 + g;
                bfr[nt][0] = ub(Vs[k + t][c]);
                bfr[nt][1] = ub(Vs[k + t + 4][c]);
            }
#pragma unroll
            for (int mt = 0; mt < 2; mt++) {
                int r = warpM + mt * 16 + g;
                unsigned af[4] = { ub(Ps[r][k + t]),     ub(Ps[r + 8][k + t]),
                                   ub(Ps[r][k + t + 4]), ub(Ps[r + 8][k + t + 4]) };
#pragma unroll
                for (int nt = 0; nt < 4; nt++) mma_tf32(acc[mt][nt], af, bfr[nt]);
            }
        }
        __syncthreads();
    }

#pragma unroll
    for (int mt = 0; mt < 2; mt++) {
        int r0 = browi + warpM + mt * 16 + g;
        size_t base0 = ((size_t)b * SEQ + r0) * DMODEL + (size_t)h * DHEAD;
#pragma unroll
        for (int nt = 0; nt < 4; nt++) {
            int c = warpN + nt * 8 + 2 * t;
            *(float2*)&g_X[base0 + c] = make_float2(acc[mt][nt][0], acc[mt][nt][1]);
            *(float2*)&g_X[base0 + (size_t)8 * DMODEL + c] = make_float2(acc[mt][nt][2], acc[mt][nt][3]);
        }
    }
}

// ---------------------------------------------------------------------------
// Launch
// ---------------------------------------------------------------------------
extern "C" void kernel_launch(void* const* d_in, const int* in_sizes, int n_in,
                              void* d_out, int out_size)
{
    const float* query = (const float*)d_in[0];
    const float* key_  = (const float*)d_in[1];
    const float* value = (const float*)d_in[2];
    const float* Wq = (const float*)d_in[3];
    const float* bq = (const float*)d_in[4];
    const float* Wk = (const float*)d_in[5];
    const float* bk = (const float*)d_in[6];
    const float* Wv = (const float*)d_in[7];
    const float* bv = (const float*)d_in[8];
    const float* Wo = (const float*)d_in[9];
    const float* bo = (const float*)d_in[10];
    float* out = (float*)d_out;

    float *Qp, *Kp, *Vp, *Xp;
    cudaGetSymbolAddress((void**)&Qp, g_Q);
    cudaGetSymbolAddress((void**)&Kp, g_K);
    cudaGetSymbolAddress((void**)&Vp, g_V);
    cudaGetSymbolAddress((void**)&Xp, g_X);

    dim3 blk(256);

    proj_tf32<<<dim3(DMODEL / 128, NTOK / 128, 3), blk>>>(
        query, key_, value, Wq, Wk, Wv, bq, bk, bv, Qp, Kp, Vp);

    qk_tf32<<<dim3(SEQ / 128, SEQ / 128, NBH), blk>>>();
    stats_reduce<<<dim3(SEQ / 256, NBH), blk>>>();
    av_tf32<<<dim3(SEQ / 128, NBH), blk>>>();

    proj_tf32<<<dim3(DMODEL / 128, NTOK / 128, 1), blk>>>(
        Xp, Xp, Xp, Wo, Wo, Wo, bo, bo, bo, out, out, out);
}

// round 11
// speedup vs baseline: 1.0008x; 1.0008x over previous
#include <cuda_runtime.h>
#include <cuda_fp16.h>
#include <math.h>

#define BB      2
#define SEQ     2048
#define DMODEL  1024
#define NHEAD   16
#define DHEAD   64
#define NTOK    (BB * SEQ)        // 4096
#define NBH     (BB * NHEAD)      // 32
#define NITILE  (SEQ / 128)       // 16
#define ATTN_SCALE 0.125f         // 1/sqrt(64)

// ---------------------------------------------------------------------------
// Scratch
// ---------------------------------------------------------------------------
__device__ float  g_Q [(size_t)NTOK * DMODEL];
__device__ float  g_K [(size_t)NTOK * DMODEL];
__device__ float  g_V [(size_t)NTOK * DMODEL];
__device__ float  g_X [(size_t)NTOK * DMODEL];
__device__ __half g_SC[(size_t)NBH * SEQ * SEQ];    // scaled scores, fp16 (268MB)
__device__ float  g_PM[(size_t)NBH * NITILE * SEQ]; // per-itile col max
__device__ float  g_PS[(size_t)NBH * NITILE * SEQ]; // per-itile col sumexp
__device__ float  g_CM[NBH * SEQ];                  // global col max
__device__ float  g_CR[NBH * SEQ];                  // global 1/sum

// ---------------------------------------------------------------------------
// Helpers
// ---------------------------------------------------------------------------
__device__ __forceinline__ float tfbits(float x) {
    unsigned r;
    asm("cvt.rna.tf32.f32 %0, %1;" : "=r"(r) : "f"(x));
    return __uint_as_float(r);
}
__device__ __forceinline__ float4 tf4(float4 v) {
    return make_float4(tfbits(v.x), tfbits(v.y), tfbits(v.z), tfbits(v.w));
}
__device__ __forceinline__ unsigned ub(float x) { return __float_as_uint(x); }

__device__ __forceinline__ void mma_tf32(float* c, const unsigned* a, const unsigned* b) {
    asm volatile(
        "mma.sync.aligned.m16n8k8.row.col.f32.tf32.tf32.f32 "
        "{%0,%1,%2,%3}, {%4,%5,%6,%7}, {%8,%9}, {%0,%1,%2,%3};"
        : "+f"(c[0]), "+f"(c[1]), "+f"(c[2]), "+f"(c[3])
        : "r"(a[0]), "r"(a[1]), "r"(a[2]), "r"(a[3]), "r"(b[0]), "r"(b[1]));
}

// ---------------------------------------------------------------------------
// Projection GEMM (tf32, pre-converted smem): C[M,1024] = A[M,1024] @ W + bias
// 128x128 block, BK=32, register-staged LDG->cvt->STS (R7-verified structure).
// gridDim.z selects the (A,W,bias,C) set.
// ---------------------------------------------------------------------------
__global__ __launch_bounds__(256, 2) void proj_tf32(
    const float* __restrict__ A0, const float* __restrict__ A1, const float* __restrict__ A2,
    const float* __restrict__ W0, const float* __restrict__ W1, const float* __restrict__ W2,
    const float* __restrict__ b0_, const float* __restrict__ b1_, const float* __restrict__ b2_,
    float* __restrict__ C0, float* __restrict__ C1, float* __restrict__ C2)
{
    constexpr int N = DMODEL, K = DMODEL;
    __shared__ float As[128][36];    // [m][k]; frag banks 4g+t distinct
    __shared__ float Bs[32][136];    // [k][n]; frag banks 8t+g distinct

    const int z = blockIdx.z;
    const float* A    = z == 0 ? A0  : (z == 1 ? A1  : A2);
    const float* W    = z == 0 ? W0  : (z == 1 ? W1  : W2);
    const float* bias = z == 0 ? b0_ : (z == 1 ? b1_ : b2_);
    float*       C    = z == 0 ? C0  : (z == 1 ? C1  : C2);

    const int tid  = threadIdx.x;
    const int brow = blockIdx.y * 128;
    const int bcol = blockIdx.x * 128;
    const int w = tid >> 5, lane = tid & 31;
    const int g = lane >> 2, t = lane & 3;
    const int warpM = (w >> 2) * 64, warpN = (w & 3) * 32;

    const int ar = tid >> 3, ac4 = (tid & 7) * 4;    // A: rows ar+i*32, k-cols ac4
    const int br = tid >> 5, bc4 = (tid & 31) * 4;   // B: rows br+i*8,  n-cols bc4

    const float* Ap = A + (size_t)(brow + ar) * K + ac4;
    const float* Wp = W + (size_t)br * N + bcol + bc4;

    float4 ra[4], rb[4];
#pragma unroll
    for (int i = 0; i < 4; i++) ra[i] = *(const float4*)(Ap + (size_t)i * 32 * K);
#pragma unroll
    for (int i = 0; i < 4; i++) rb[i] = *(const float4*)(Wp + (size_t)i * 8 * N);

    float acc[4][4][4];
#pragma unroll
    for (int mt = 0; mt < 4; mt++)
#pragma unroll
        for (int nt = 0; nt < 4; nt++)
#pragma unroll
            for (int i = 0; i < 4; i++) acc[mt][nt][i] = 0.f;

    for (int k0 = 0; k0 < K; k0 += 32) {
#pragma unroll
        for (int i = 0; i < 4; i++) *(float4*)&As[ar + i * 32][ac4] = tf4(ra[i]);
#pragma unroll
        for (int i = 0; i < 4; i++) *(float4*)&Bs[br + i * 8][bc4]  = tf4(rb[i]);
        __syncthreads();

        if (k0 + 32 < K) {
#pragma unroll
            for (int i = 0; i < 4; i++)
                ra[i] = *(const float4*)(Ap + k0 + 32 + (size_t)i * 32 * K);
#pragma unroll
            for (int i = 0; i < 4; i++)
                rb[i] = *(const float4*)(Wp + (size_t)(k0 + 32 + i * 8) * N);
        }

#pragma unroll
        for (int ks = 0; ks < 4; ks++) {
            const int k = ks * 8;
            unsigned bfr[4][2];
#pragma unroll
            for (int nt = 0; nt < 4; nt++) {
                int c = warpN + nt * 8 + g;
                bfr[nt][0] = ub(Bs[k + t][c]);
                bfr[nt][1] = ub(Bs[k + t + 4][c]);
            }
#pragma unroll
            for (int mt = 0; mt < 4; mt++) {
                int r = warpM + mt * 16 + g;
                unsigned af[4] = { ub(As[r][k + t]),     ub(As[r + 8][k + t]),
                                   ub(As[r][k + t + 4]), ub(As[r + 8][k + t + 4]) };
#pragma unroll
                for (int nt = 0; nt < 4; nt++) mma_tf32(acc[mt][nt], af, bfr[nt]);
            }
        }
        __syncthreads();
    }

#pragma unroll
    for (int mt = 0; mt < 4; mt++) {
        int r0 = brow + warpM + mt * 16 + g;
#pragma unroll
        for (int nt = 0; nt < 4; nt++) {
            int c = bcol + warpN + nt * 8 + 2 * t;
            float bb0 = bias[c], bb1 = bias[c + 1];
            *(float2*)&C[(size_t)r0 * N + c]       = make_float2(acc[mt][nt][0] + bb0, acc[mt][nt][1] + bb1);
            *(float2*)&C[(size_t)(r0 + 8) * N + c] = make_float2(acc[mt][nt][2] + bb0, acc[mt][nt][3] + bb1);
        }
    }
}

// ---------------------------------------------------------------------------
// QK^T scores (tf32 NT) + fused per-tile column stats.
// Stores fp16 scaled scores; fp32 (max, sumexp) partials per 128-row i-tile.
// ---------------------------------------------------------------------------
__global__ __launch_bounds__(256, 2) void qk_tf32()
{
    __shared__ float Qs[128][36];
    __shared__ float Ks[128][36];
    __shared__ float Sm2[2][128];
    __shared__ float Ss2[2][128];

    const int tid = threadIdx.x;
    const int bh  = blockIdx.z, b = bh >> 4, h = bh & 15;
    const int browi = blockIdx.y * 128;
    const int bcolj = blockIdx.x * 128;

    const float* Qb = g_Q + (size_t)b * SEQ * DMODEL + (size_t)h * DHEAD;
    const float* Kb = g_K + (size_t)b * SEQ * DMODEL + (size_t)h * DHEAD;
    __half*      Cb = g_SC + (size_t)bh * SEQ * SEQ;

    const int w = tid >> 5, lane = tid & 31;
    const int g = lane >> 2, t = lane & 3;
    const int warpM = (w >> 2) * 64, warpN = (w & 3) * 32;

    const int lr = tid >> 3, lc4 = (tid & 7) * 4;
    const float* Qp = Qb + (size_t)(browi + lr) * DMODEL + lc4;
    const float* Kp = Kb + (size_t)(bcolj + lr) * DMODEL + lc4;

    float4 rq[4], rk[4];
#pragma unroll
    for (int i = 0; i < 4; i++) {
        rq[i] = *(const float4*)(Qp + (size_t)i * 32 * DMODEL);
        rk[i] = *(const float4*)(Kp + (size_t)i * 32 * DMODEL);
    }

    float acc[4][4][4];
#pragma unroll
    for (int mt = 0; mt < 4; mt++)
#pragma unroll
        for (int nt = 0; nt < 4; nt++)
#pragma unroll
            for (int i = 0; i < 4; i++) acc[mt][nt][i] = 0.f;

    for (int k0 = 0; k0 < DHEAD; k0 += 32) {
#pragma unroll
        for (int i = 0; i < 4; i++) {
            *(float4*)&Qs[lr + i * 32][lc4] = tf4(rq[i]);
            *(float4*)&Ks[lr + i * 32][lc4] = tf4(rk[i]);
        }
        __syncthreads();

        if (k0 == 0) {
#pragma unroll
            for (int i = 0; i < 4; i++) {
                rq[i] = *(const float4*)(Qp + 32 + (size_t)i * 32 * DMODEL);
                rk[i] = *(const float4*)(Kp + 32 + (size_t)i * 32 * DMODEL);
            }
        }

#pragma unroll
        for (int ks = 0; ks < 4; ks++) {
            const int k = ks * 8;
            unsigned bfr[4][2];
#pragma unroll
            for (int nt = 0; nt < 4; nt++) {
                int c = warpN + nt * 8 + g;
                bfr[nt][0] = ub(Ks[c][k + t]);
                bfr[nt][1] = ub(Ks[c][k + t + 4]);
            }
#pragma unroll
            for (int mt = 0; mt < 4; mt++) {
                int r = warpM + mt * 16 + g;
                unsigned af[4] = { ub(Qs[r][k + t]),     ub(Qs[r + 8][k + t]),
                                   ub(Qs[r][k + t + 4]), ub(Qs[r + 8][k + t + 4]) };
#pragma unroll
                for (int nt = 0; nt < 4; nt++) mma_tf32(acc[mt][nt], af, bfr[nt]);
            }
        }
        __syncthreads();
    }

    // scale, store fp16 scores
#pragma unroll
    for (int mt = 0; mt < 4; mt++)
#pragma unroll
        for (int nt = 0; nt < 4; nt++)
#pragma unroll
            for (int i = 0; i < 4; i++) acc[mt][nt][i] *= ATTN_SCALE;

#pragma unroll
    for (int mt = 0; mt < 4; mt++) {
        int r0 = browi + warpM + mt * 16 + g;
#pragma unroll
        for (int nt = 0; nt < 4; nt++) {
            int c = bcolj + warpN + nt * 8 + 2 * t;
            *(__half2*)&Cb[(size_t)r0 * SEQ + c] =
                __floats2half2_rn(acc[mt][nt][0], acc[mt][nt][1]);
            *(__half2*)&Cb[(size_t)(r0 + 8) * SEQ + c] =
                __floats2half2_rn(acc[mt][nt][2], acc[mt][nt][3]);
        }
    }

    // fused column stats over this tile's 128 rows (fp32)
#pragma unroll
    for (int nt = 0; nt < 4; nt++) {
        float m0 = -1e30f, m1 = -1e30f;
#pragma unroll
        for (int mt = 0; mt < 4; mt++) {
            m0 = fmaxf(m0, fmaxf(acc[mt][nt][0], acc[mt][nt][2]));
            m1 = fmaxf(m1, fmaxf(acc[mt][nt][1], acc[mt][nt][3]));
        }
#pragma unroll
        for (int off = 4; off < 32; off <<= 1) {
            m0 = fmaxf(m0, __shfl_xor_sync(0xffffffffu, m0, off));
            m1 = fmaxf(m1, __shfl_xor_sync(0xffffffffu, m1, off));
        }
        float s0 = 0.f, s1 = 0.f;
#pragma unroll
        for (int mt = 0; mt < 4; mt++) {
            s0 += __expf(acc[mt][nt][0] - m0) + __expf(acc[mt][nt][2] - m0);
            s1 += __expf(acc[mt][nt][1] - m1) + __expf(acc[mt][nt][3] - m1);
        }
#pragma unroll
        for (int off = 4; off < 32; off <<= 1) {
            s0 += __shfl_xor_sync(0xffffffffu, s0, off);
            s1 += __shfl_xor_sync(0xffffffffu, s1, off);
        }
        if (g == 0) {
            int c = warpN + nt * 8 + 2 * t;
            int half_ = w >> 2;
            Sm2[half_][c]     = m0;  Ss2[half_][c]     = s0;
            Sm2[half_][c + 1] = m1;  Ss2[half_][c + 1] = s1;
        }
    }
    __syncthreads();
    if (tid < 128) {
        float ma = Sm2[0][tid], mb = Sm2[1][tid];
        float m  = fmaxf(ma, mb);
        float s  = Ss2[0][tid] * __expf(ma - m) + Ss2[1][tid] * __expf(mb - m);
        size_t off = ((size_t)bh * NITILE + blockIdx.y) * SEQ + bcolj + tid;
        g_PM[off] = m;
        g_PS[off] = s;
    }
}

// ---------------------------------------------------------------------------
// Merge per-itile partials -> global column (max, 1/sum).
// ---------------------------------------------------------------------------
__global__ __launch_bounds__(256) void stats_reduce()
{
    const int bh = blockIdx.y;
    const int j  = blockIdx.x * 256 + threadIdx.x;

    float m = -1e30f, s = 0.f;
#pragma unroll
    for (int it = 0; it < NITILE; it++) {
        size_t off = ((size_t)bh * NITILE + it) * SEQ + j;
        float mp = g_PM[off], sp = g_PS[off];
        float mn = fmaxf(m, mp);
        s = s * __expf(m - mn) + sp * __expf(mp - mn);
        m = mn;
    }
    g_CM[bh * SEQ + j] = m;
    g_CR[bh * SEQ + j] = 1.0f / s;
}

// ---------------------------------------------------------------------------
// AV GEMM (tf32) with fused softmax on P fill, fp16 score loads.
// 128(i) x 64(d) block, BK=32 over j (R7-verified structure).
// ---------------------------------------------------------------------------
__global__ __launch_bounds__(256, 2) void av_tf32()
{
    __shared__ float Ps[128][36];   // [i][j-local]
    __shared__ float Vs[32][72];    // [j-local][d]

    const int tid = threadIdx.x;
    const int bh  = blockIdx.y, b = bh >> 4, h = bh & 15;
    const int browi = blockIdx.x * 128;

    const __half* Sb = g_SC + (size_t)bh * SEQ * SEQ;
    const float*  cm = g_CM + bh * SEQ;
    const float*  cr = g_CR + bh * SEQ;
    const float*  Vb = g_V + (size_t)b * SEQ * DMODEL + (size_t)h * DHEAD;

    const int w = tid >> 5, lane = tid & 31;
    const int g = lane >> 2, t = lane & 3;
    const int warpM = (w >> 1) * 32, warpN = (w & 1) * 32;

    const int pr = tid >> 3, pc4 = (tid & 7) * 4;    // P: rows pr+i*32, cols pc4..+3
    const int vr = tid >> 4, vc4 = (tid & 15) * 4;   // V: rows vr+i*16

    uint2  rs[4];                 // 4 half scores per row, 4 rows
    float4 rv[2], rm, rr;
#pragma unroll
    for (int i = 0; i < 4; i++)
        rs[i] = *(const uint2*)(Sb + (size_t)(browi + pr + i * 32) * SEQ + pc4);
#pragma unroll
    for (int i = 0; i < 2; i++)
        rv[i] = *(const float4*)(Vb + (size_t)(vr + i * 16) * DMODEL + vc4);
    rm = *(const float4*)&cm[pc4];
    rr = *(const float4*)&cr[pc4];

    float acc[2][4][4];
#pragma unroll
    for (int mt = 0; mt < 2; mt++)
#pragma unroll
        for (int nt = 0; nt < 4; nt++)
#pragma unroll
            for (int i = 0; i < 4; i++) acc[mt][nt][i] = 0.f;

    for (int k0 = 0; k0 < SEQ; k0 += 32) {
        // P fill: half->float, exp-normalize, tf32 cvt
#pragma unroll
        for (int i = 0; i < 4; i++) {
            float2 f01 = __half22float2(*(__half2*)&rs[i].x);
            float2 f23 = __half22float2(*(__half2*)&rs[i].y);
            *(float4*)&Ps[pr + i * 32][pc4] = make_float4(
                tfbits(__expf(f01.x - rm.x) * rr.x),
                tfbits(__expf(f01.y - rm.y) * rr.y),
                tfbits(__expf(f23.x - rm.z) * rr.z),
                tfbits(__expf(f23.y - rm.w) * rr.w));
        }
#pragma unroll
        for (int i = 0; i < 2; i++) *(float4*)&Vs[vr + i * 16][vc4] = tf4(rv[i]);
        __syncthreads();

        if (k0 + 32 < SEQ) {
            const int kn = k0 + 32;
#pragma unroll
            for (int i = 0; i < 4; i++)
                rs[i] = *(const uint2*)(Sb + (size_t)(browi + pr + i * 32) * SEQ + kn + pc4);
#pragma unroll
            for (int i = 0; i < 2; i++)
                rv[i] = *(const float4*)(Vb + (size_t)(kn + vr + i * 16) * DMODEL + vc4);
            rm = *(const float4*)&cm[kn + pc4];
            rr = *(const float4*)&cr[kn + pc4];
        }

#pragma unroll
        for (int ks = 0; ks < 4; ks++) {
            const int k = ks * 8;
            unsigned bfr[4][2];
#pragma unroll
            for (int nt = 0; nt < 4; nt++) {
                int c = warpN + nt * 8 + g;
                bfr[nt][0] = ub(Vs[k + t][c]);
                bfr[nt][1] = ub(Vs[k + t + 4][c]);
            }
#pragma unroll
            for (int mt = 0; mt < 2; mt++) {
                int r = warpM + mt * 16 + g;
                unsigned af[4] = { ub(Ps[r][k + t]),     ub(Ps[r + 8][k + t]),
                                   ub(Ps[r][k + t + 4]), ub(Ps[r + 8][k + t + 4]) };
#pragma unroll
                for (int nt = 0; nt < 4; nt++) mma_tf32(acc[mt][nt], af, bfr[nt]);
            }
        }
        __syncthreads();
    }

#pragma unroll
    for (int mt = 0; mt < 2; mt++) {
        int r0 = browi + warpM + mt * 16 + g;
        size_t base0 = ((size_t)b * SEQ + r0) * DMODEL + (size_t)h * DHEAD;
#pragma unroll
        for (int nt = 0; nt < 4; nt++) {
            int c = warpN + nt * 8 + 2 * t;
            *(float2*)&g_X[base0 + c] = make_float2(acc[mt][nt][0], acc[mt][nt][1]);
            *(float2*)&g_X[base0 + (size_t)8 * DMODEL + c] = make_float2(acc[mt][nt][2], acc[mt][nt][3]);
        }
    }
}

// ---------------------------------------------------------------------------
// Launch
// ---------------------------------------------------------------------------
extern "C" void kernel_launch(void* const* d_in, const int* in_sizes, int n_in,
                              void* d_out, int out_size)
{
    const float* query = (const float*)d_in[0];
    const float* key_  = (const float*)d_in[1];
    const float* value = (const float*)d_in[2];
    const float* Wq = (const float*)d_in[3];
    const float* bq = (const float*)d_in[4];
    const float* Wk = (const float*)d_in[5];
    const float* bk = (const float*)d_in[6];
    const float* Wv = (const float*)d_in[7];
    const float* bv = (const float*)d_in[8];
    const float* Wo = (const float*)d_in[9];
    const float* bo = (const float*)d_in[10];
    float* out = (float*)d_out;

    float *Qp, *Kp, *Vp, *Xp;
    cudaGetSymbolAddress((void**)&Qp, g_Q);
    cudaGetSymbolAddress((void**)&Kp, g_K);
    cudaGetSymbolAddress((void**)&Vp, g_V);
    cudaGetSymbolAddress((void**)&Xp, g_X);

    dim3 blk(256);

    proj_tf32<<<dim3(DMODEL / 128, NTOK / 128, 3), blk>>>(
        query, key_, value, Wq, Wk, Wv, bq, bk, bv, Qp, Kp, Vp);

    qk_tf32<<<dim3(SEQ / 128, SEQ / 128, NBH), blk>>>();
    stats_reduce<<<dim3(SEQ / 256, NBH), blk>>>();
    av_tf32<<<dim3(SEQ / 128, NBH), blk>>>();

    proj_tf32<<<dim3(DMODEL / 128, NTOK / 128, 1), blk>>>(
        Xp, Xp, Xp, Wo, Wo, Wo, bo, bo, bo, out, out, out);
}